// round 13
// baseline (speedup 1.0000x reference)
#include <cuda_runtime.h>
#include <cuda_fp16.h>

#define N_ENTS  50000
#define N_EDGES 500000
#define RANK    128
#define SLOPE   0.22916666666666666f   // (1/8 + 1/3)/2

typedef unsigned int u32;

// ---------------- device scratch (allocation-free rule) ----------------
// g_deg zeroed by scanC at end-of-use; g_deg0_count zeroed by fixup1 (tail).
__device__ int   g_deg[N_ENTS];
__device__ int   g_rowptr[N_ENTS + 1];
__device__ int   g_cursor[N_ENTS];
__device__ int2  g_coledge[N_EDGES];          // (src, etype) per CSR slot
__device__ float g_h1[(size_t)N_ENTS * RANK];
__device__ float g_sumrel[(size_t)N_ENTS * RANK];
// A fp16 [N_ENTS][256]: cols 0-127 = scaled agg, cols 128-255 = h
__device__ __half g_Af[(size_t)N_ENTS * 256];
// W fp16 [layer][n=128][k=256]: hi part and residual (k<128: Wn, else Wl)
__device__ __half g_Wh[2 * 128 * 256];
__device__ __half g_Wr[2 * 128 * 256];
__device__ int   g_deg0_list[N_ENTS];
__device__ int   g_deg0_count;
#define SNB 49                                 // ceil(50000/1024)
__device__ int   g_bsum[SNB];

// ---------------- helpers ----------------
__device__ __forceinline__ u32 smem_u32(const void* p) {
    u32 a;
    asm("{ .reg .u64 t; cvta.to.shared.u64 t, %1; cvt.u32.u64 %0, t; }"
        : "=r"(a) : "l"(p));
    return a;
}
__device__ __forceinline__ void cpa16z(u32 saddr, const void* g, int sz) {
    asm volatile("cp.async.ca.shared.global [%0], [%1], 16, %2;"
                 :: "r"(saddr), "l"(g), "r"(sz) : "memory");
}
__device__ __forceinline__ void cpa16(u32 saddr, const void* g) {
    asm volatile("cp.async.ca.shared.global [%0], [%1], 16;"
                 :: "r"(saddr), "l"(g) : "memory");
}
__device__ __forceinline__ void cpa_commit() {
    asm volatile("cp.async.commit_group;" ::: "memory");
}
__device__ __forceinline__ void cpa_wait1() {
    asm volatile("cp.async.wait_group 1;" ::: "memory");
}
__device__ __forceinline__ void ldmx4(u32* r, u32 addr) {
    asm volatile("ldmatrix.sync.aligned.m8n8.x4.shared.b16 {%0,%1,%2,%3}, [%4];"
                 : "=r"(r[0]), "=r"(r[1]), "=r"(r[2]), "=r"(r[3]) : "r"(addr));
}
__device__ __forceinline__ void mma16816h(float* c, const u32* a, const u32* b) {
    asm volatile(
        "mma.sync.aligned.m16n8k16.row.col.f32.f16.f16.f32 "
        "{%0,%1,%2,%3}, {%4,%5,%6,%7}, {%8,%9}, {%0,%1,%2,%3};"
        : "+f"(c[0]), "+f"(c[1]), "+f"(c[2]), "+f"(c[3])
        : "r"(a[0]), "r"(a[1]), "r"(a[2]), "r"(a[3]), "r"(b[0]), "r"(b[1]));
}
__device__ __forceinline__ u32 h2u(__half2 h) {
    return *reinterpret_cast<u32*>(&h);
}

// ---------------- launch 1: hist + weight split + ent fp16 ----------------
#define EB   ((N_EDGES + 255) / 256)
#define WTB  (2 * 128 * 256 / 256)                 // 256
#define ENTB ((N_ENTS * 32 + 255) / 256)           // 6250
__global__ void histprep_kernel(const int* __restrict__ dst,
                                const float* __restrict__ Wn,
                                const float* __restrict__ Wl,
                                const float* __restrict__ ent) {
    int b = blockIdx.x;
    if (b < EB) {
        int e = b * 256 + threadIdx.x;
        if (e < N_EDGES) atomicAdd(&g_deg[dst[e]], 1);
    } else if (b < EB + WTB) {
        int idx = (b - EB) * 256 + threadIdx.x;    // [l][n][k]
        int k = idx & 255;
        int l = idx >> 15;
        int n = (idx >> 8) & 127;
        const float* W = (k < 128) ? (Wn + l * 16384 + k * 128 + n)
                                   : (Wl + l * 16384 + (k - 128) * 128 + n);
        float v = *W;
        __half hi = __float2half_rn(v);
        g_Wh[idx] = hi;
        g_Wr[idx] = __float2half_rn(v - __half2float(hi));
    } else {
        int idx = (b - EB - WTB) * 256 + threadIdx.x;
        if (idx >= N_ENTS * 32) return;
        int row = idx >> 5, q = idx & 31;
        float4 v = reinterpret_cast<const float4*>(ent + (size_t)row * RANK)[q];
        uint2 o;
        o.x = h2u(__floats2half2_rn(v.x, v.y));
        o.y = h2u(__floats2half2_rn(v.z, v.w));
        *reinterpret_cast<uint2*>(g_Af + (size_t)row * 256 + 128 + q * 4) = o;
    }
}

// ---------------- CSR scans (scanB folded into scanC) ----------------
__global__ void scanA_kernel() {
    __shared__ int red[1024];
    int i = blockIdx.x * 1024 + threadIdx.x;
    int d = (i < N_ENTS) ? g_deg[i] : 0;
    red[threadIdx.x] = d;
    __syncthreads();
    for (int off = 512; off > 0; off >>= 1) {
        if (threadIdx.x < off) red[threadIdx.x] += red[threadIdx.x + off];
        __syncthreads();
    }
    if (threadIdx.x == 0) g_bsum[blockIdx.x] = red[0];
}

__global__ void scanC_kernel() {
    __shared__ int s[1024];
    __shared__ int pre[64];
    int tid = threadIdx.x;
    if (tid < 64) pre[tid] = (tid < blockIdx.x && tid < SNB) ? g_bsum[tid] : 0;
    int i = blockIdx.x * 1024 + tid;
    int d = (i < N_ENTS) ? g_deg[i] : 0;
    s[tid] = d;
    __syncthreads();
    if (tid == 0) {
        int o = 0;
        for (int j = 0; j < 64; j++) o += pre[j];
        pre[0] = o;                       // block offset
    }
    for (int off = 1; off < 1024; off <<= 1) {
        int v = (tid >= off) ? s[tid - off] : 0;
        __syncthreads();
        s[tid] += v;
        __syncthreads();
    }
    if (i < N_ENTS) {
        int excl = s[tid] - d + pre[0];
        g_rowptr[i] = excl;
        g_cursor[i] = excl;
        if (d == 0) {
            int p = atomicAdd(&g_deg0_count, 1);
            g_deg0_list[p] = i;
        }
        g_deg[i] = 0;                      // reset for next replay
    }
    if (i == 0) g_rowptr[N_ENTS] = N_EDGES;
}

__global__ void fill_kernel(const int* __restrict__ src, const int* __restrict__ dst,
                            const int* __restrict__ et) {
    int e = blockIdx.x * blockDim.x + threadIdx.x;
    if (e < N_EDGES) {
        int d = dst[e];
        int p = atomicAdd(&g_cursor[d], 1);
        g_coledge[p] = make_int2(src[e], et[e]);
    }
}

// ---------------- aggregation (R11-proven fp32-gather body) ----------------
// mode 0: gather h+rel fp32, store sumrel fp32, write agg fp16 cols 0-127
// mode 1: gather h fp32 only, add stored sumrel
__global__ void agg_kernel(const float* __restrict__ h_ext,
                           const float* __restrict__ rel,
                           const float* __restrict__ norm, int mode) {
    const float* __restrict__ h = h_ext ? h_ext : (const float*)g_h1;
    int w = (blockIdx.x * blockDim.x + threadIdx.x) >> 5;
    if (w >= N_ENTS) return;
    int lane = threadIdx.x & 31;
    int e0 = g_rowptr[w], e1 = g_rowptr[w + 1];

    float4 acc = make_float4(0.f, 0.f, 0.f, 0.f);
    float4 racc = make_float4(0.f, 0.f, 0.f, 0.f);
    for (int base = e0; base < e1; base += 32) {
        int mys = 0, myt = 0;
        if (base + lane < e1) {
            int2 ed = g_coledge[base + lane];
            mys = ed.x; myt = ed.y;
        }
        int cnt = e1 - base; if (cnt > 32) cnt = 32;
        int j = 0;
        for (; j + 2 <= cnt; j += 2) {
            int s0 = __shfl_sync(0xffffffffu, mys, j);
            int s1 = __shfl_sync(0xffffffffu, mys, j + 1);
            float4 a0 = reinterpret_cast<const float4*>(h + (size_t)s0 * RANK)[lane];
            float4 a1 = reinterpret_cast<const float4*>(h + (size_t)s1 * RANK)[lane];
            acc.x += a0.x + a1.x; acc.y += a0.y + a1.y;
            acc.z += a0.z + a1.z; acc.w += a0.w + a1.w;
            if (mode == 0) {
                int t0 = __shfl_sync(0xffffffffu, myt, j);
                int t1 = __shfl_sync(0xffffffffu, myt, j + 1);
                float4 r0 = reinterpret_cast<const float4*>(rel + (size_t)t0 * RANK)[lane];
                float4 r1 = reinterpret_cast<const float4*>(rel + (size_t)t1 * RANK)[lane];
                racc.x += r0.x + r1.x; racc.y += r0.y + r1.y;
                racc.z += r0.z + r1.z; racc.w += r0.w + r1.w;
            }
        }
        for (; j < cnt; j++) {
            int s = __shfl_sync(0xffffffffu, mys, j);
            float4 a = reinterpret_cast<const float4*>(h + (size_t)s * RANK)[lane];
            acc.x += a.x; acc.y += a.y; acc.z += a.z; acc.w += a.w;
            if (mode == 0) {
                int t = __shfl_sync(0xffffffffu, myt, j);
                float4 r = reinterpret_cast<const float4*>(rel + (size_t)t * RANK)[lane];
                racc.x += r.x; racc.y += r.y; racc.z += r.z; racc.w += r.w;
            }
        }
    }
    if (mode == 0) {
        reinterpret_cast<float4*>(g_sumrel + (size_t)w * RANK)[lane] = racc;
    } else {
        racc = reinterpret_cast<const float4*>(g_sumrel + (size_t)w * RANK)[lane];
    }
    float nm = norm[w];
    uint2 o;
    o.x = h2u(__floats2half2_rn((acc.x + racc.x) * nm, (acc.y + racc.y) * nm));
    o.y = h2u(__floats2half2_rn((acc.z + racc.z) * nm, (acc.w + racc.w) * nm));
    *reinterpret_cast<uint2*>(g_Af + (size_t)w * 256 + lane * 4) = o;
}

// ---------------- 2-pass fp16 mma.sync GEMM, BM=64, cp.async 2-stage ------
// D = A@Whi + A@Wlo, K=256 in 8 chunks of 32. 8 warps: 4 m16 x 2 n64.
#define NCH    8
#define TROWB  80
#define TILEA  (64 * TROWB)      // 5120
#define TILEBB (128 * TROWB)     // 10240
#define GEMM_SMEM (2 * TILEA + 4 * TILEBB)   // 51200
__global__ void __launch_bounds__(256, 4)
gemm_kernel(int layer, float* __restrict__ out_ext, int write_h) {
    extern __shared__ __align__(16) char smem[];
    float* __restrict__ outf = out_ext ? out_ext : (float*)g_h1;

    const int tid = threadIdx.x;
    const int lane = tid & 31;
    const int wid = tid >> 5;
    const int warp_m = wid & 3;      // rows warp_m*16
    const int warp_n = wid >> 2;     // cols warp_n*64
    const int block_row = blockIdx.x * 64;

    const u32 sAu  = smem_u32(smem);                 // [2][TILEA]
    const u32 sBhU = sAu + 2 * TILEA;                // [2][TILEBB]
    const u32 sBrU = sBhU + 2 * TILEBB;              // [2][TILEBB]

    const int l_row = tid >> 2;                      // 0..63
    const int l_c16 = (tid & 3) * 16;

    const int a_q = lane >> 3;
    const int a_row = (lane & 7) + (a_q & 1) * 8;
    const int a_kb = (a_q >> 1) * 16;
    const int b_q = lane >> 3;
    const int b_row = ((b_q >> 1) * 8) + (lane & 7);
    const int b_kb = (b_q & 1) * 16;

    float c[8][4];
#pragma unroll
    for (int n = 0; n < 8; n++)
#pragma unroll
        for (int r = 0; r < 4; r++) c[n][r] = 0.f;

    const char* __restrict__ Wh = (const char*)(g_Wh + ((size_t)layer << 15));
    const char* __restrict__ Wr = (const char*)(g_Wr + ((size_t)layer << 15));

    auto issue = [&](int kc, int buf) {
        const int kbyte = kc * 64;
        int grow = block_row + l_row;
        cpa16z(sAu + buf * TILEA + l_row * TROWB + l_c16,
               (const char*)g_Af + (size_t)grow * 512 + kbyte + l_c16,
               (grow < N_ENTS) ? 16 : 0);
#pragma unroll
        for (int i = 0; i < 2; i++) {
            int row = l_row + i * 64;
            cpa16(sBhU + buf * TILEBB + row * TROWB + l_c16,
                  Wh + (size_t)row * 512 + kbyte + l_c16);
            cpa16(sBrU + buf * TILEBB + row * TROWB + l_c16,
                  Wr + (size_t)row * 512 + kbyte + l_c16);
        }
    };

    issue(0, 0); cpa_commit();
    issue(1, 1); cpa_commit();

    for (int kc = 0; kc < NCH; kc++) {
        const int buf = kc & 1;
        cpa_wait1();
        __syncthreads();
        const u32 aBase  = sAu  + buf * TILEA;
        const u32 bhBase = sBhU + buf * TILEBB;
        const u32 brBase = sBrU + buf * TILEBB;
#pragma unroll
        for (int j = 0; j < 2; j++) {
            u32 aa[4];
            ldmx4(aa, aBase + (warp_m * 16 + a_row) * TROWB + j * 32 + a_kb);
#pragma unroll
            for (int p = 0; p < 4; p++) {
                u32 bbh[4], bbr[4];
                u32 boff = (warp_n * 64 + p * 16 + b_row) * TROWB + j * 32 + b_kb;
                ldmx4(bbh, bhBase + boff);
                ldmx4(bbr, brBase + boff);
                mma16816h(c[2 * p],     aa, bbh);
                mma16816h(c[2 * p + 1], aa, bbh + 2);
                mma16816h(c[2 * p],     aa, bbr);
                mma16816h(c[2 * p + 1], aa, bbr + 2);
            }
        }
        __syncthreads();
        if (kc + 2 < NCH) issue(kc + 2, buf);
        cpa_commit();
    }

    // epilogue: leaky relu, fp32 out (+ fp16 h for next layer)
    const int er = lane >> 2;
    const int ec = (lane & 3) * 2;
#pragma unroll
    for (int half = 0; half < 2; half++) {
        int grow = block_row + warp_m * 16 + er + half * 8;
        if (grow >= N_ENTS) continue;
#pragma unroll
        for (int n = 0; n < 8; n++) {
            int col = warp_n * 64 + n * 8 + ec;
            float v0 = c[n][half * 2 + 0];
            float v1 = c[n][half * 2 + 1];
            v0 = (v0 >= 0.f) ? v0 : v0 * SLOPE;
            v1 = (v1 >= 0.f) ? v1 : v1 * SLOPE;
            *reinterpret_cast<float2*>(outf + (size_t)grow * RANK + col) =
                make_float2(v0, v1);
            if (write_h)
                *reinterpret_cast<u32*>(g_Af + (size_t)grow * 256 + 128 + col) =
                    h2u(__floats2half2_rn(v0, v1));
        }
    }
}

// ---------------- deg-0 fixup ----------------
__global__ void fixup_kernel(const float* __restrict__ h_ext,
                             const float* __restrict__ Wa,
                             float* __restrict__ out_ext, int write_h,
                             int zero_after) {
    const float* __restrict__ h = h_ext ? h_ext : (const float*)g_h1;
    float* __restrict__ Out = out_ext ? out_ext : (float*)g_h1;
    int wg = (blockIdx.x * blockDim.x + threadIdx.x) >> 5;
    int lane = threadIdx.x & 31;
    int nwarp = (gridDim.x * blockDim.x) >> 5;
    int cnt = g_deg0_count;
    for (int idx = wg; idx < cnt; idx += nwarp) {
        int v = g_deg0_list[idx];
        const float* hr = h + (size_t)v * RANK;
        float4 acc = make_float4(0.f, 0.f, 0.f, 0.f);
        for (int k = 0; k < RANK; k++) {
            float a = hr[k];
            float4 wv = reinterpret_cast<const float4*>(Wa + (size_t)k * RANK)[lane];
            acc.x += a * wv.x; acc.y += a * wv.y;
            acc.z += a * wv.z; acc.w += a * wv.w;
        }
        float f0 = (acc.x >= 0.f) ? acc.x : acc.x * SLOPE;
        float f1 = (acc.y >= 0.f) ? acc.y : acc.y * SLOPE;
        float f2 = (acc.z >= 0.f) ? acc.z : acc.z * SLOPE;
        float f3 = (acc.w >= 0.f) ? acc.w : acc.w * SLOPE;
        reinterpret_cast<float4*>(Out + (size_t)v * RANK)[lane] =
            make_float4(f0, f1, f2, f3);
        if (write_h) {
            uint2 o;
            o.x = h2u(__floats2half2_rn(f0, f1));
            o.y = h2u(__floats2half2_rn(f2, f3));
            *reinterpret_cast<uint2*>(g_Af + (size_t)v * 256 + 128 + lane * 4) = o;
        }
    }
    if (zero_after) {                 // single-block launch only
        __syncthreads();
        if (threadIdx.x == 0) g_deg0_count = 0;
    }
}

// ---------------- launch ----------------
extern "C" void kernel_launch(void* const* d_in, const int* in_sizes, int n_in,
                              void* d_out, int out_size) {
    const float* ent  = (const float*)d_in[0];
    const float* rel  = (const float*)d_in[1];
    const float* norm = (const float*)d_in[2];
    const float* Wn   = (const float*)d_in[3];
    const float* Wl   = (const float*)d_in[4];
    const float* Wa   = (const float*)d_in[5];
    const int*   src  = (const int*)d_in[6];
    const int*   dst  = (const int*)d_in[7];
    const int*   et   = (const int*)d_in[8];
    float* out = (float*)d_out;

    const int AGB = (N_ENTS * 32 + 255) / 256;
    const int GB  = (N_ENTS + 63) / 64;          // 782
    const int WSTRIDE = RANK * RANK;

    cudaFuncSetAttribute(gemm_kernel,
                         cudaFuncAttributeMaxDynamicSharedMemorySize, GEMM_SMEM);

    histprep_kernel<<<EB + WTB + ENTB, 256>>>(dst, Wn, Wl, ent);  // 1
    scanA_kernel<<<SNB, 1024>>>();                        // 2
    scanC_kernel<<<SNB, 1024>>>();                        // 3
    fill_kernel<<<EB, 256>>>(src, dst, et);               // 4
    agg_kernel<<<AGB, 256>>>(ent, rel, norm, 0);          // 5
    gemm_kernel<<<GB, 256, GEMM_SMEM>>>(0, nullptr, 1);   // 6
    fixup_kernel<<<8, 256>>>(ent, Wa + 0 * WSTRIDE, nullptr, 1, 0);   // 7
    agg_kernel<<<AGB, 256>>>(nullptr, rel, norm, 1);      // 8
    gemm_kernel<<<GB, 256, GEMM_SMEM>>>(1, out, 0);       // 9
    fixup_kernel<<<1, 256>>>(nullptr, Wa + 1 * WSTRIDE, out, 0, 1);   // 10
}

// round 14
// speedup vs baseline: 1.2520x; 1.2520x over previous
#include <cuda_runtime.h>
#include <cuda_fp16.h>

#define N_ENTS  50000
#define N_EDGES 500000
#define RANK    128
#define SLOPE   0.22916666666666666f   // (1/8 + 1/3)/2

typedef unsigned int u32;

// ---------------- device scratch (allocation-free rule) ----------------
// g_deg zeroed by scanC at end-of-use; g_deg0_count zeroed by fixup1 (tail).
__device__ int   g_deg[N_ENTS];
__device__ int   g_rowptr[N_ENTS + 1];
__device__ int   g_cursor[N_ENTS];
__device__ int2  g_coledge[N_EDGES];          // (src, etype) per CSR slot
__device__ float g_h1[(size_t)N_ENTS * RANK];
__device__ float g_sumrel[(size_t)N_ENTS * RANK];
// A fp16 [N_ENTS][256]: cols 0-127 = scaled agg, cols 128-255 = h
__device__ __half g_Af[(size_t)N_ENTS * 256];
// W fp16 [layer][n=128][k=256] (k<128: Wn, else Wl)
__device__ __half g_Wh[2 * 128 * 256];
__device__ int   g_deg0_list[N_ENTS];
__device__ int   g_deg0_count;
#define SNB 49                                 // ceil(50000/1024)
__device__ int   g_bsum[SNB];

// ---------------- helpers ----------------
__device__ __forceinline__ u32 smem_u32(const void* p) {
    u32 a;
    asm("{ .reg .u64 t; cvta.to.shared.u64 t, %1; cvt.u32.u64 %0, t; }"
        : "=r"(a) : "l"(p));
    return a;
}
__device__ __forceinline__ void cpa16z(u32 saddr, const void* g, int sz) {
    asm volatile("cp.async.ca.shared.global [%0], [%1], 16, %2;"
                 :: "r"(saddr), "l"(g), "r"(sz) : "memory");
}
__device__ __forceinline__ void cpa16(u32 saddr, const void* g) {
    asm volatile("cp.async.ca.shared.global [%0], [%1], 16;"
                 :: "r"(saddr), "l"(g) : "memory");
}
__device__ __forceinline__ void cpa_commit() {
    asm volatile("cp.async.commit_group;" ::: "memory");
}
__device__ __forceinline__ void cpa_wait1() {
    asm volatile("cp.async.wait_group 1;" ::: "memory");
}
__device__ __forceinline__ void ldmx4(u32* r, u32 addr) {
    asm volatile("ldmatrix.sync.aligned.m8n8.x4.shared.b16 {%0,%1,%2,%3}, [%4];"
                 : "=r"(r[0]), "=r"(r[1]), "=r"(r[2]), "=r"(r[3]) : "r"(addr));
}
__device__ __forceinline__ void mma16816h(float* c, const u32* a, const u32* b) {
    asm volatile(
        "mma.sync.aligned.m16n8k16.row.col.f32.f16.f16.f32 "
        "{%0,%1,%2,%3}, {%4,%5,%6,%7}, {%8,%9}, {%0,%1,%2,%3};"
        : "+f"(c[0]), "+f"(c[1]), "+f"(c[2]), "+f"(c[3])
        : "r"(a[0]), "r"(a[1]), "r"(a[2]), "r"(a[3]), "r"(b[0]), "r"(b[1]));
}
__device__ __forceinline__ u32 h2u(__half2 h) {
    return *reinterpret_cast<u32*>(&h);
}

// ---------------- launch 1: hist + W fp16 + ent fp16 ----------------
#define EB   ((N_EDGES + 255) / 256)
#define WTB  (2 * 128 * 256 / 256)                 // 256
#define ENTB ((N_ENTS * 32 + 255) / 256)           // 6250
__global__ void histprep_kernel(const int* __restrict__ dst,
                                const float* __restrict__ Wn,
                                const float* __restrict__ Wl,
                                const float* __restrict__ ent) {
    int b = blockIdx.x;
    if (b < EB) {
        int e = b * 256 + threadIdx.x;
        if (e < N_EDGES) atomicAdd(&g_deg[dst[e]], 1);
    } else if (b < EB + WTB) {
        int idx = (b - EB) * 256 + threadIdx.x;    // [l][n][k]
        int k = idx & 255;
        int l = idx >> 15;
        int n = (idx >> 8) & 127;
        const float* W = (k < 128) ? (Wn + l * 16384 + k * 128 + n)
                                   : (Wl + l * 16384 + (k - 128) * 128 + n);
        g_Wh[idx] = __float2half_rn(*W);
    } else {
        int idx = (b - EB - WTB) * 256 + threadIdx.x;
        if (idx >= N_ENTS * 32) return;
        int row = idx >> 5, q = idx & 31;
        float4 v = reinterpret_cast<const float4*>(ent + (size_t)row * RANK)[q];
        uint2 o;
        o.x = h2u(__floats2half2_rn(v.x, v.y));
        o.y = h2u(__floats2half2_rn(v.z, v.w));
        *reinterpret_cast<uint2*>(g_Af + (size_t)row * 256 + 128 + q * 4) = o;
    }
}

// ---------------- CSR scans (scanB folded into scanC) ----------------
__global__ void scanA_kernel() {
    __shared__ int red[1024];
    int i = blockIdx.x * 1024 + threadIdx.x;
    int d = (i < N_ENTS) ? g_deg[i] : 0;
    red[threadIdx.x] = d;
    __syncthreads();
    for (int off = 512; off > 0; off >>= 1) {
        if (threadIdx.x < off) red[threadIdx.x] += red[threadIdx.x + off];
        __syncthreads();
    }
    if (threadIdx.x == 0) g_bsum[blockIdx.x] = red[0];
}

__global__ void scanC_kernel() {
    __shared__ int s[1024];
    __shared__ int pre[64];
    int tid = threadIdx.x;
    if (tid < 64) pre[tid] = (tid < blockIdx.x && tid < SNB) ? g_bsum[tid] : 0;
    int i = blockIdx.x * 1024 + tid;
    int d = (i < N_ENTS) ? g_deg[i] : 0;
    s[tid] = d;
    __syncthreads();
    if (tid == 0) {
        int o = 0;
        for (int j = 0; j < 64; j++) o += pre[j];
        pre[0] = o;                       // block offset
    }
    for (int off = 1; off < 1024; off <<= 1) {
        int v = (tid >= off) ? s[tid - off] : 0;
        __syncthreads();
        s[tid] += v;
        __syncthreads();
    }
    if (i < N_ENTS) {
        int excl = s[tid] - d + pre[0];
        g_rowptr[i] = excl;
        g_cursor[i] = excl;
        if (d == 0) {
            int p = atomicAdd(&g_deg0_count, 1);
            g_deg0_list[p] = i;
        }
        g_deg[i] = 0;                      // reset for next replay
    }
    if (i == 0) g_rowptr[N_ENTS] = N_EDGES;
}

__global__ void fill_kernel(const int* __restrict__ src, const int* __restrict__ dst,
                            const int* __restrict__ et) {
    int e = blockIdx.x * blockDim.x + threadIdx.x;
    if (e < N_EDGES) {
        int d = dst[e];
        int p = atomicAdd(&g_cursor[d], 1);
        g_coledge[p] = make_int2(src[e], et[e]);
    }
}

// ---------------- aggregation (R11-proven fp32-gather body) ----------------
// mode 0: gather h+rel fp32, store sumrel fp32, write agg fp16 cols 0-127
// mode 1: gather h fp32 only, add stored sumrel
__global__ void agg_kernel(const float* __restrict__ h_ext,
                           const float* __restrict__ rel,
                           const float* __restrict__ norm, int mode) {
    const float* __restrict__ h = h_ext ? h_ext : (const float*)g_h1;
    int w = (blockIdx.x * blockDim.x + threadIdx.x) >> 5;
    if (w >= N_ENTS) return;
    int lane = threadIdx.x & 31;
    int e0 = g_rowptr[w], e1 = g_rowptr[w + 1];

    float4 acc = make_float4(0.f, 0.f, 0.f, 0.f);
    float4 racc = make_float4(0.f, 0.f, 0.f, 0.f);
    for (int base = e0; base < e1; base += 32) {
        int mys = 0, myt = 0;
        if (base + lane < e1) {
            int2 ed = g_coledge[base + lane];
            mys = ed.x; myt = ed.y;
        }
        int cnt = e1 - base; if (cnt > 32) cnt = 32;
        int j = 0;
        for (; j + 2 <= cnt; j += 2) {
            int s0 = __shfl_sync(0xffffffffu, mys, j);
            int s1 = __shfl_sync(0xffffffffu, mys, j + 1);
            float4 a0 = reinterpret_cast<const float4*>(h + (size_t)s0 * RANK)[lane];
            float4 a1 = reinterpret_cast<const float4*>(h + (size_t)s1 * RANK)[lane];
            acc.x += a0.x + a1.x; acc.y += a0.y + a1.y;
            acc.z += a0.z + a1.z; acc.w += a0.w + a1.w;
            if (mode == 0) {
                int t0 = __shfl_sync(0xffffffffu, myt, j);
                int t1 = __shfl_sync(0xffffffffu, myt, j + 1);
                float4 r0 = reinterpret_cast<const float4*>(rel + (size_t)t0 * RANK)[lane];
                float4 r1 = reinterpret_cast<const float4*>(rel + (size_t)t1 * RANK)[lane];
                racc.x += r0.x + r1.x; racc.y += r0.y + r1.y;
                racc.z += r0.z + r1.z; racc.w += r0.w + r1.w;
            }
        }
        for (; j < cnt; j++) {
            int s = __shfl_sync(0xffffffffu, mys, j);
            float4 a = reinterpret_cast<const float4*>(h + (size_t)s * RANK)[lane];
            acc.x += a.x; acc.y += a.y; acc.z += a.z; acc.w += a.w;
            if (mode == 0) {
                int t = __shfl_sync(0xffffffffu, myt, j);
                float4 r = reinterpret_cast<const float4*>(rel + (size_t)t * RANK)[lane];
                racc.x += r.x; racc.y += r.y; racc.z += r.z; racc.w += r.w;
            }
        }
    }
    if (mode == 0) {
        reinterpret_cast<float4*>(g_sumrel + (size_t)w * RANK)[lane] = racc;
    } else {
        racc = reinterpret_cast<const float4*>(g_sumrel + (size_t)w * RANK)[lane];
    }
    float nm = norm[w];
    uint2 o;
    o.x = h2u(__floats2half2_rn((acc.x + racc.x) * nm, (acc.y + racc.y) * nm));
    o.y = h2u(__floats2half2_rn((acc.z + racc.z) * nm, (acc.w + racc.w) * nm));
    *reinterpret_cast<uint2*>(g_Af + (size_t)w * 256 + lane * 4) = o;
}

// ---------------- single-pass fp16 mma.sync GEMM (R11 geometry) ----------
// D = A@W, K=256 in 8 chunks of 32, BM=128. 8 warps: 4 m32 x 2 n64.
#define NCH   8
#define TROWB 80
#define TILEB (128 * TROWB)
#define GEMM_SMEM (4 * TILEB)      // {A,B} x 2 buffers = 40960 B
__global__ void __launch_bounds__(256, 2)
gemm_kernel(int layer, float* __restrict__ out_ext, int write_h) {
    extern __shared__ __align__(16) char smem[];
    float* __restrict__ outf = out_ext ? out_ext : (float*)g_h1;

    const int tid = threadIdx.x;
    const int lane = tid & 31;
    const int wid = tid >> 5;
    const int warp_m = wid & 3;
    const int warp_n = wid >> 2;
    const int block_row = blockIdx.x * 128;

    const u32 sAu = smem_u32(smem);                // [2][TILEB]
    const u32 sBu = sAu + 2 * TILEB;               // [2][TILEB]

    const int l_row0 = tid >> 2;                   // rows 0..63 (i=0), +64 (i=1)
    const int l_c16  = (tid & 3) * 16;

    const int a_q = lane >> 3;
    const int a_row = (lane & 7) + (a_q & 1) * 8;
    const int a_kb = (a_q >> 1) * 16;
    const int b_q = lane >> 3;
    const int b_row = ((b_q >> 1) * 8) + (lane & 7);
    const int b_kb = (b_q & 1) * 16;

    float c[2][8][4];
#pragma unroll
    for (int t = 0; t < 2; t++)
#pragma unroll
        for (int n = 0; n < 8; n++)
#pragma unroll
            for (int r = 0; r < 4; r++) c[t][n][r] = 0.f;

    const char* __restrict__ Wh = (const char*)(g_Wh + ((size_t)layer << 15));

    auto issue = [&](int kc, int buf) {
        const int kbyte = kc * 64;
#pragma unroll
        for (int i = 0; i < 2; i++) {
            int row = l_row0 + i * 64;
            int grow = block_row + row;
            cpa16z(sAu + buf * TILEB + row * TROWB + l_c16,
                   (const char*)g_Af + (size_t)grow * 512 + kbyte + l_c16,
                   (grow < N_ENTS) ? 16 : 0);
            cpa16(sBu + buf * TILEB + row * TROWB + l_c16,
                  Wh + (size_t)row * 512 + kbyte + l_c16);
        }
    };

    issue(0, 0); cpa_commit();
    issue(1, 1); cpa_commit();

    for (int kc = 0; kc < NCH; kc++) {
        const int buf = kc & 1;
        cpa_wait1();
        __syncthreads();
        const u32 aBase = sAu + buf * TILEB;
        const u32 bBase = sBu + buf * TILEB;
#pragma unroll
        for (int j = 0; j < 2; j++) {
            u32 aa[2][4];
#pragma unroll
            for (int t = 0; t < 2; t++)
                ldmx4(aa[t], aBase + (warp_m * 32 + t * 16 + a_row) * TROWB + j * 32 + a_kb);
#pragma unroll
            for (int p = 0; p < 4; p++) {
                u32 bb[4];
                ldmx4(bb, bBase + (warp_n * 64 + p * 16 + b_row) * TROWB + j * 32 + b_kb);
#pragma unroll
                for (int t = 0; t < 2; t++) {
                    mma16816h(c[t][2 * p],     aa[t], bb);
                    mma16816h(c[t][2 * p + 1], aa[t], bb + 2);
                }
            }
        }
        __syncthreads();
        if (kc + 2 < NCH) issue(kc + 2, buf);
        cpa_commit();
    }

    const int er = lane >> 2;
    const int ec = (lane & 3) * 2;
#pragma unroll
    for (int t = 0; t < 2; t++) {
#pragma unroll
        for (int half = 0; half < 2; half++) {
            int grow = block_row + warp_m * 32 + t * 16 + er + half * 8;
            if (grow >= N_ENTS) continue;
#pragma unroll
            for (int n = 0; n < 8; n++) {
                int col = warp_n * 64 + n * 8 + ec;
                float v0 = c[t][n][half * 2 + 0];
                float v1 = c[t][n][half * 2 + 1];
                v0 = (v0 >= 0.f) ? v0 : v0 * SLOPE;
                v1 = (v1 >= 0.f) ? v1 : v1 * SLOPE;
                *reinterpret_cast<float2*>(outf + (size_t)grow * RANK + col) =
                    make_float2(v0, v1);
                if (write_h)
                    *reinterpret_cast<u32*>(g_Af + (size_t)grow * 256 + 128 + col) =
                        h2u(__floats2half2_rn(v0, v1));
            }
        }
    }
}

// ---------------- deg-0 fixup ----------------
__global__ void fixup_kernel(const float* __restrict__ h_ext,
                             const float* __restrict__ Wa,
                             float* __restrict__ out_ext, int write_h,
                             int zero_after) {
    const float* __restrict__ h = h_ext ? h_ext : (const float*)g_h1;
    float* __restrict__ Out = out_ext ? out_ext : (float*)g_h1;
    int wg = (blockIdx.x * blockDim.x + threadIdx.x) >> 5;
    int lane = threadIdx.x & 31;
    int nwarp = (gridDim.x * blockDim.x) >> 5;
    int cnt = g_deg0_count;
    for (int idx = wg; idx < cnt; idx += nwarp) {
        int v = g_deg0_list[idx];
        const float* hr = h + (size_t)v * RANK;
        float4 acc = make_float4(0.f, 0.f, 0.f, 0.f);
        for (int k = 0; k < RANK; k++) {
            float a = hr[k];
            float4 wv = reinterpret_cast<const float4*>(Wa + (size_t)k * RANK)[lane];
            acc.x += a * wv.x; acc.y += a * wv.y;
            acc.z += a * wv.z; acc.w += a * wv.w;
        }
        float f0 = (acc.x >= 0.f) ? acc.x : acc.x * SLOPE;
        float f1 = (acc.y >= 0.f) ? acc.y : acc.y * SLOPE;
        float f2 = (acc.z >= 0.f) ? acc.z : acc.z * SLOPE;
        float f3 = (acc.w >= 0.f) ? acc.w : acc.w * SLOPE;
        reinterpret_cast<float4*>(Out + (size_t)v * RANK)[lane] =
            make_float4(f0, f1, f2, f3);
        if (write_h) {
            uint2 o;
            o.x = h2u(__floats2half2_rn(f0, f1));
            o.y = h2u(__floats2half2_rn(f2, f3));
            *reinterpret_cast<uint2*>(g_Af + (size_t)v * 256 + 128 + lane * 4) = o;
        }
    }
    if (zero_after) {                 // single-block launch only
        __syncthreads();
        if (threadIdx.x == 0) g_deg0_count = 0;
    }
}

// ---------------- launch ----------------
extern "C" void kernel_launch(void* const* d_in, const int* in_sizes, int n_in,
                              void* d_out, int out_size) {
    const float* ent  = (const float*)d_in[0];
    const float* rel  = (const float*)d_in[1];
    const float* norm = (const float*)d_in[2];
    const float* Wn   = (const float*)d_in[3];
    const float* Wl   = (const float*)d_in[4];
    const float* Wa   = (const float*)d_in[5];
    const int*   src  = (const int*)d_in[6];
    const int*   dst  = (const int*)d_in[7];
    const int*   et   = (const int*)d_in[8];
    float* out = (float*)d_out;

    const int AGB = (N_ENTS * 32 + 255) / 256;
    const int GB  = (N_ENTS + 127) / 128;
    const int WSTRIDE = RANK * RANK;

    cudaFuncSetAttribute(gemm_kernel,
                         cudaFuncAttributeMaxDynamicSharedMemorySize, GEMM_SMEM);

    histprep_kernel<<<EB + WTB + ENTB, 256>>>(dst, Wn, Wl, ent);  // 1
    scanA_kernel<<<SNB, 1024>>>();                        // 2
    scanC_kernel<<<SNB, 1024>>>();                        // 3
    fill_kernel<<<EB, 256>>>(src, dst, et);               // 4
    agg_kernel<<<AGB, 256>>>(ent, rel, norm, 0);          // 5
    gemm_kernel<<<GB, 256, GEMM_SMEM>>>(0, nullptr, 1);   // 6
    fixup_kernel<<<8, 256>>>(ent, Wa + 0 * WSTRIDE, nullptr, 1, 0);   // 7
    agg_kernel<<<AGB, 256>>>(nullptr, rel, norm, 1);      // 8
    gemm_kernel<<<GB, 256, GEMM_SMEM>>>(1, out, 0);       // 9
    fixup_kernel<<<1, 256>>>(nullptr, Wa + 1 * WSTRIDE, out, 0, 1);   // 10
}

// round 15
// speedup vs baseline: 1.2592x; 1.0058x over previous
#include <cuda_runtime.h>
#include <cuda_fp16.h>

#define N_ENTS  50000
#define N_EDGES 500000
#define N_RELS  200
#define RANK    128
#define SLOPE   0.22916666666666666f   // (1/8 + 1/3)/2

typedef unsigned int u32;

// ---------------- device scratch (allocation-free rule) ----------------
// g_deg zeroed by scan_kernel at end-of-use; g_flag zeroed by fill_kernel;
// g_deg0_count zeroed by fixup1 (tail). All BSS-zero at load.
__device__ int   g_deg[N_ENTS];
__device__ int   g_rowptr[N_ENTS + 1];
__device__ int   g_cursor[N_ENTS];
__device__ int2  g_coledge[N_EDGES];          // (src, etype) per CSR slot
__device__ float g_h1[(size_t)N_ENTS * RANK];
__device__ float g_sumrel[(size_t)N_ENTS * RANK];
// A fp16 [N_ENTS][256]: cols 0-127 = scaled agg, cols 128-255 = h
__device__ __half g_Af[(size_t)N_ENTS * 256];
// rel fp16 [N_RELS][128] (agg0 gather only)
__device__ __half g_relh[N_RELS * RANK];
// W fp16 [layer][n=128][k=256] (k<128: Wn, else Wl)
__device__ __half g_Wh[2 * 128 * 256];
__device__ int   g_deg0_list[N_ENTS];
__device__ int   g_deg0_count;
#define SNB 49                                 // ceil(50000/1024)
__device__ int   g_bsum[SNB];
__device__ int   g_flag[SNB];

// ---------------- helpers ----------------
__device__ __forceinline__ u32 smem_u32(const void* p) {
    u32 a;
    asm("{ .reg .u64 t; cvta.to.shared.u64 t, %1; cvt.u32.u64 %0, t; }"
        : "=r"(a) : "l"(p));
    return a;
}
__device__ __forceinline__ void cpa16z(u32 saddr, const void* g, int sz) {
    asm volatile("cp.async.ca.shared.global [%0], [%1], 16, %2;"
                 :: "r"(saddr), "l"(g), "r"(sz) : "memory");
}
__device__ __forceinline__ void cpa16(u32 saddr, const void* g) {
    asm volatile("cp.async.ca.shared.global [%0], [%1], 16;"
                 :: "r"(saddr), "l"(g) : "memory");
}
__device__ __forceinline__ void cpa_commit() {
    asm volatile("cp.async.commit_group;" ::: "memory");
}
__device__ __forceinline__ void cpa_wait1() {
    asm volatile("cp.async.wait_group 1;" ::: "memory");
}
__device__ __forceinline__ void ldmx4(u32* r, u32 addr) {
    asm volatile("ldmatrix.sync.aligned.m8n8.x4.shared.b16 {%0,%1,%2,%3}, [%4];"
                 : "=r"(r[0]), "=r"(r[1]), "=r"(r[2]), "=r"(r[3]) : "r"(addr));
}
__device__ __forceinline__ void mma16816h(float* c, const u32* a, const u32* b) {
    asm volatile(
        "mma.sync.aligned.m16n8k16.row.col.f32.f16.f16.f32 "
        "{%0,%1,%2,%3}, {%4,%5,%6,%7}, {%8,%9}, {%0,%1,%2,%3};"
        : "+f"(c[0]), "+f"(c[1]), "+f"(c[2]), "+f"(c[3])
        : "r"(a[0]), "r"(a[1]), "r"(a[2]), "r"(a[3]), "r"(b[0]), "r"(b[1]));
}
__device__ __forceinline__ u32 h2u(__half2 h) {
    return *reinterpret_cast<u32*>(&h);
}
// gather 4 halves (8B) per lane from a row, widen to float4
__device__ __forceinline__ float4 ldh4(const __half* row, int lane) {
    uint2 q = reinterpret_cast<const uint2*>(row)[lane];
    float2 f0 = __half22float2(*reinterpret_cast<__half2*>(&q.x));
    float2 f1 = __half22float2(*reinterpret_cast<__half2*>(&q.y));
    return make_float4(f0.x, f0.y, f1.x, f1.y);
}

// ---------------- launch 1: hist + W fp16 + ent fp16 + rel fp16 -----------
#define EB   ((N_EDGES + 255) / 256)
#define WTB  (2 * 128 * 256 / 256)                 // 256
#define ENTB ((N_ENTS * 32 + 255) / 256)           // 6250
#define RELB (N_RELS * RANK / 256)                 // 100
__global__ void histprep_kernel(const int* __restrict__ dst,
                                const float* __restrict__ Wn,
                                const float* __restrict__ Wl,
                                const float* __restrict__ ent,
                                const float* __restrict__ rel) {
    int b = blockIdx.x;
    if (b < EB) {
        int e = b * 256 + threadIdx.x;
        if (e < N_EDGES) atomicAdd(&g_deg[dst[e]], 1);
    } else if (b < EB + WTB) {
        int idx = (b - EB) * 256 + threadIdx.x;    // [l][n][k]
        int k = idx & 255;
        int l = idx >> 15;
        int n = (idx >> 8) & 127;
        const float* W = (k < 128) ? (Wn + l * 16384 + k * 128 + n)
                                   : (Wl + l * 16384 + (k - 128) * 128 + n);
        g_Wh[idx] = __float2half_rn(*W);
    } else if (b < EB + WTB + ENTB) {
        int idx = (b - EB - WTB) * 256 + threadIdx.x;
        if (idx >= N_ENTS * 32) return;
        int row = idx >> 5, q = idx & 31;
        float4 v = reinterpret_cast<const float4*>(ent + (size_t)row * RANK)[q];
        uint2 o;
        o.x = h2u(__floats2half2_rn(v.x, v.y));
        o.y = h2u(__floats2half2_rn(v.z, v.w));
        *reinterpret_cast<uint2*>(g_Af + (size_t)row * 256 + 128 + q * 4) = o;
    } else {
        int idx = (b - EB - WTB - ENTB) * 256 + threadIdx.x;
        if (idx < N_RELS * RANK) g_relh[idx] = __float2half_rn(rel[idx]);
    }
}

// ---------------- single-kernel scan (decoupled lookback, 49 blocks) ------
__global__ void scan_kernel() {
    __shared__ int s[1024];
    __shared__ int pre[64];
    const int tid = threadIdx.x;
    const int b = blockIdx.x;
    const int i = b * 1024 + tid;
    const int d = (i < N_ENTS) ? g_deg[i] : 0;
    s[tid] = d;
    __syncthreads();
    // inclusive scan within block
    for (int off = 1; off < 1024; off <<= 1) {
        int v = (tid >= off) ? s[tid - off] : 0;
        __syncthreads();
        s[tid] += v;
        __syncthreads();
    }
    // publish block total, then look back at predecessors (L2 atomics only)
    if (tid == 0) {
        g_bsum[b] = s[1023];
        __threadfence();
        atomicExch(&g_flag[b], 1);
    }
    if (tid < 64) pre[tid] = 0;
    __syncthreads();
    if (tid < b) {                      // b <= 48, fits in two warps
        while (atomicAdd(&g_flag[tid], 0) == 0) { }
        pre[tid] = atomicAdd(&g_bsum[tid], 0);   // L2-coherent read
    }
    __syncthreads();
    if (tid == 0) {
        int o = 0;
        for (int j = 0; j < b; j++) o += pre[j];
        pre[0] = o;
    }
    __syncthreads();
    if (i < N_ENTS) {
        int excl = s[tid] - d + ((b > 0) ? pre[0] : 0);
        g_rowptr[i] = excl;
        g_cursor[i] = excl;
        if (d == 0) {
            int p = atomicAdd(&g_deg0_count, 1);
            g_deg0_list[p] = i;
        }
        g_deg[i] = 0;                   // reset for next replay
    }
    if (i == 0) g_rowptr[N_ENTS] = N_EDGES;
}

__global__ void fill_kernel(const int* __restrict__ src, const int* __restrict__ dst,
                            const int* __restrict__ et) {
    int e = blockIdx.x * blockDim.x + threadIdx.x;
    if (e < SNB) g_flag[e] = 0;        // reset lookback flags for next replay
    if (e < N_EDGES) {
        int d = dst[e];
        int p = atomicAdd(&g_cursor[d], 1);
        g_coledge[p] = make_int2(src[e], et[e]);
    }
}

// ---------------- aggregation (fp32 h gather; fp16 rel gather) ------------
// mode 0: gather h fp32 + rel fp16, store sumrel fp32, write agg fp16
// mode 1: gather h fp32 only, add stored sumrel
__global__ void agg_kernel(const float* __restrict__ h_ext,
                           const float* __restrict__ norm, int mode) {
    const float* __restrict__ h = h_ext ? h_ext : (const float*)g_h1;
    int w = (blockIdx.x * blockDim.x + threadIdx.x) >> 5;
    if (w >= N_ENTS) return;
    int lane = threadIdx.x & 31;
    int e0 = g_rowptr[w], e1 = g_rowptr[w + 1];

    float4 acc = make_float4(0.f, 0.f, 0.f, 0.f);
    float4 racc = make_float4(0.f, 0.f, 0.f, 0.f);
    for (int base = e0; base < e1; base += 32) {
        int mys = 0, myt = 0;
        if (base + lane < e1) {
            int2 ed = g_coledge[base + lane];
            mys = ed.x; myt = ed.y;
        }
        int cnt = e1 - base; if (cnt > 32) cnt = 32;
        int j = 0;
        for (; j + 2 <= cnt; j += 2) {
            int s0 = __shfl_sync(0xffffffffu, mys, j);
            int s1 = __shfl_sync(0xffffffffu, mys, j + 1);
            float4 a0 = reinterpret_cast<const float4*>(h + (size_t)s0 * RANK)[lane];
            float4 a1 = reinterpret_cast<const float4*>(h + (size_t)s1 * RANK)[lane];
            acc.x += a0.x + a1.x; acc.y += a0.y + a1.y;
            acc.z += a0.z + a1.z; acc.w += a0.w + a1.w;
            if (mode == 0) {
                int t0 = __shfl_sync(0xffffffffu, myt, j);
                int t1 = __shfl_sync(0xffffffffu, myt, j + 1);
                float4 r0 = ldh4(g_relh + (size_t)t0 * RANK, lane);
                float4 r1 = ldh4(g_relh + (size_t)t1 * RANK, lane);
                racc.x += r0.x + r1.x; racc.y += r0.y + r1.y;
                racc.z += r0.z + r1.z; racc.w += r0.w + r1.w;
            }
        }
        for (; j < cnt; j++) {
            int s = __shfl_sync(0xffffffffu, mys, j);
            float4 a = reinterpret_cast<const float4*>(h + (size_t)s * RANK)[lane];
            acc.x += a.x; acc.y += a.y; acc.z += a.z; acc.w += a.w;
            if (mode == 0) {
                int t = __shfl_sync(0xffffffffu, myt, j);
                float4 r = ldh4(g_relh + (size_t)t * RANK, lane);
                racc.x += r.x; racc.y += r.y; racc.z += r.z; racc.w += r.w;
            }
        }
    }
    if (mode == 0) {
        reinterpret_cast<float4*>(g_sumrel + (size_t)w * RANK)[lane] = racc;
    } else {
        racc = reinterpret_cast<const float4*>(g_sumrel + (size_t)w * RANK)[lane];
    }
    float nm = norm[w];
    uint2 o;
    o.x = h2u(__floats2half2_rn((acc.x + racc.x) * nm, (acc.y + racc.y) * nm));
    o.y = h2u(__floats2half2_rn((acc.z + racc.z) * nm, (acc.w + racc.w) * nm));
    *reinterpret_cast<uint2*>(g_Af + (size_t)w * 256 + lane * 4) = o;
}

// ---------------- single-pass fp16 mma.sync GEMM (R14-proven) -------------
#define NCH   8
#define TROWB 80
#define TILEB (128 * TROWB)
#define GEMM_SMEM (4 * TILEB)      // 40960 B
__global__ void __launch_bounds__(256, 2)
gemm_kernel(int layer, float* __restrict__ out_ext, int write_h) {
    extern __shared__ __align__(16) char smem[];
    float* __restrict__ outf = out_ext ? out_ext : (float*)g_h1;

    const int tid = threadIdx.x;
    const int lane = tid & 31;
    const int wid = tid >> 5;
    const int warp_m = wid & 3;
    const int warp_n = wid >> 2;
    const int block_row = blockIdx.x * 128;

    const u32 sAu = smem_u32(smem);
    const u32 sBu = sAu + 2 * TILEB;

    const int l_row0 = tid >> 2;
    const int l_c16  = (tid & 3) * 16;

    const int a_q = lane >> 3;
    const int a_row = (lane & 7) + (a_q & 1) * 8;
    const int a_kb = (a_q >> 1) * 16;
    const int b_q = lane >> 3;
    const int b_row = ((b_q >> 1) * 8) + (lane & 7);
    const int b_kb = (b_q & 1) * 16;

    float c[2][8][4];
#pragma unroll
    for (int t = 0; t < 2; t++)
#pragma unroll
        for (int n = 0; n < 8; n++)
#pragma unroll
            for (int r = 0; r < 4; r++) c[t][n][r] = 0.f;

    const char* __restrict__ Wh = (const char*)(g_Wh + ((size_t)layer << 15));

    auto issue = [&](int kc, int buf) {
        const int kbyte = kc * 64;
#pragma unroll
        for (int i = 0; i < 2; i++) {
            int row = l_row0 + i * 64;
            int grow = block_row + row;
            cpa16z(sAu + buf * TILEB + row * TROWB + l_c16,
                   (const char*)g_Af + (size_t)grow * 512 + kbyte + l_c16,
                   (grow < N_ENTS) ? 16 : 0);
            cpa16(sBu + buf * TILEB + row * TROWB + l_c16,
                  Wh + (size_t)row * 512 + kbyte + l_c16);
        }
    };

    issue(0, 0); cpa_commit();
    issue(1, 1); cpa_commit();

    for (int kc = 0; kc < NCH; kc++) {
        const int buf = kc & 1;
        cpa_wait1();
        __syncthreads();
        const u32 aBase = sAu + buf * TILEB;
        const u32 bBase = sBu + buf * TILEB;
#pragma unroll
        for (int j = 0; j < 2; j++) {
            u32 aa[2][4];
#pragma unroll
            for (int t = 0; t < 2; t++)
                ldmx4(aa[t], aBase + (warp_m * 32 + t * 16 + a_row) * TROWB + j * 32 + a_kb);
#pragma unroll
            for (int p = 0; p < 4; p++) {
                u32 bb[4];
                ldmx4(bb, bBase + (warp_n * 64 + p * 16 + b_row) * TROWB + j * 32 + b_kb);
#pragma unroll
                for (int t = 0; t < 2; t++) {
                    mma16816h(c[t][2 * p],     aa[t], bb);
                    mma16816h(c[t][2 * p + 1], aa[t], bb + 2);
                }
            }
        }
        __syncthreads();
        if (kc + 2 < NCH) issue(kc + 2, buf);
        cpa_commit();
    }

    const int er = lane >> 2;
    const int ec = (lane & 3) * 2;
#pragma unroll
    for (int t = 0; t < 2; t++) {
#pragma unroll
        for (int half = 0; half < 2; half++) {
            int grow = block_row + warp_m * 32 + t * 16 + er + half * 8;
            if (grow >= N_ENTS) continue;
#pragma unroll
            for (int n = 0; n < 8; n++) {
                int col = warp_n * 64 + n * 8 + ec;
                float v0 = c[t][n][half * 2 + 0];
                float v1 = c[t][n][half * 2 + 1];
                v0 = (v0 >= 0.f) ? v0 : v0 * SLOPE;
                v1 = (v1 >= 0.f) ? v1 : v1 * SLOPE;
                *reinterpret_cast<float2*>(outf + (size_t)grow * RANK + col) =
                    make_float2(v0, v1);
                if (write_h)
                    *reinterpret_cast<u32*>(g_Af + (size_t)grow * 256 + 128 + col) =
                        h2u(__floats2half2_rn(v0, v1));
            }
        }
    }
}

// ---------------- deg-0 fixup ----------------
__global__ void fixup_kernel(const float* __restrict__ h_ext,
                             const float* __restrict__ Wa,
                             float* __restrict__ out_ext, int write_h,
                             int zero_after) {
    const float* __restrict__ h = h_ext ? h_ext : (const float*)g_h1;
    float* __restrict__ Out = out_ext ? out_ext : (float*)g_h1;
    int wg = (blockIdx.x * blockDim.x + threadIdx.x) >> 5;
    int lane = threadIdx.x & 31;
    int nwarp = (gridDim.x * blockDim.x) >> 5;
    int cnt = g_deg0_count;
    for (int idx = wg; idx < cnt; idx += nwarp) {
        int v = g_deg0_list[idx];
        const float* hr = h + (size_t)v * RANK;
        float4 acc = make_float4(0.f, 0.f, 0.f, 0.f);
        for (int k = 0; k < RANK; k++) {
            float a = hr[k];
            float4 wv = reinterpret_cast<const float4*>(Wa + (size_t)k * RANK)[lane];
            acc.x += a * wv.x; acc.y += a * wv.y;
            acc.z += a * wv.z; acc.w += a * wv.w;
        }
        float f0 = (acc.x >= 0.f) ? acc.x : acc.x * SLOPE;
        float f1 = (acc.y >= 0.f) ? acc.y : acc.y * SLOPE;
        float f2 = (acc.z >= 0.f) ? acc.z : acc.z * SLOPE;
        float f3 = (acc.w >= 0.f) ? acc.w : acc.w * SLOPE;
        reinterpret_cast<float4*>(Out + (size_t)v * RANK)[lane] =
            make_float4(f0, f1, f2, f3);
        if (write_h) {
            uint2 o;
            o.x = h2u(__floats2half2_rn(f0, f1));
            o.y = h2u(__floats2half2_rn(f2, f3));
            *reinterpret_cast<uint2*>(g_Af + (size_t)v * 256 + 128 + lane * 4) = o;
        }
    }
    if (zero_after) {                 // single-block launch only
        __syncthreads();
        if (threadIdx.x == 0) g_deg0_count = 0;
    }
}

// ---------------- launch ----------------
extern "C" void kernel_launch(void* const* d_in, const int* in_sizes, int n_in,
                              void* d_out, int out_size) {
    const float* ent  = (const float*)d_in[0];
    const float* rel  = (const float*)d_in[1];
    const float* norm = (const float*)d_in[2];
    const float* Wn   = (const float*)d_in[3];
    const float* Wl   = (const float*)d_in[4];
    const float* Wa   = (const float*)d_in[5];
    const int*   src  = (const int*)d_in[6];
    const int*   dst  = (const int*)d_in[7];
    const int*   et   = (const int*)d_in[8];
    float* out = (float*)d_out;

    const int AGB = (N_ENTS * 32 + 255) / 256;
    const int GB  = (N_ENTS + 127) / 128;
    const int WSTRIDE = RANK * RANK;

    cudaFuncSetAttribute(gemm_kernel,
                         cudaFuncAttributeMaxDynamicSharedMemorySize, GEMM_SMEM);

    histprep_kernel<<<EB + WTB + ENTB + RELB, 256>>>(dst, Wn, Wl, ent, rel); // 1
    scan_kernel<<<SNB, 1024>>>();                         // 2 (lookback scan)
    fill_kernel<<<EB, 256>>>(src, dst, et);               // 3
    agg_kernel<<<AGB, 256>>>(ent, norm, 0);               // 4
    gemm_kernel<<<GB, 256, GEMM_SMEM>>>(0, nullptr, 1);   // 5
    fixup_kernel<<<8, 256>>>(ent, Wa + 0 * WSTRIDE, nullptr, 1, 0);   // 6
    agg_kernel<<<AGB, 256>>>(nullptr, norm, 1);           // 7
    gemm_kernel<<<GB, 256, GEMM_SMEM>>>(1, out, 0);       // 8
    fixup_kernel<<<1, 256>>>(nullptr, Wa + 1 * WSTRIDE, out, 0, 1);   // 9
}